// round 1
// baseline (speedup 1.0000x reference)
#include <cuda_runtime.h>
#include <math.h>

#define BB 2
#define NN 512
#define DD 256
#define NH 4
#define HD 64
#define MR (BB*NN)   // 1024 rows

// ---------------- scratch (no allocation allowed) ----------------
__device__ float g_q[MR*DD];
__device__ float g_k[MR*DD];
__device__ float g_v[MR*DD];
__device__ float g_a[MR*DD];
__device__ float g_b[MR*DD];
__device__ float g_attn[BB*NH*NN*NN];   // 8 MB
__device__ float g_ctx[MR*DD];

// ---------------- generic 64x64 tiled GEMM body (K=256) ----------------
__device__ __forceinline__ void gemm64_body(
    const float* __restrict__ A,
    const float* __restrict__ W,
    const float* __restrict__ bias,
    float* __restrict__ C,
    int m0, int n0,
    float (*As)[68], float (*Ws)[68])
{
    int tid = threadIdx.x;
    int tx = tid & 15, ty = tid >> 4;
    float acc[4][4] = {};

    for (int k0 = 0; k0 < 256; k0 += 16) {
        __syncthreads();
        // A tile 64x16 -> As[kk][r]
        #pragma unroll
        for (int t = 0; t < 4; t++) {
            int idx = tid + t * 256;
            int r = idx >> 4, c = idx & 15;
            As[c][r] = A[(m0 + r) * 256 + k0 + c];
        }
        // W tile 16x64 -> Ws[kk][c]
        #pragma unroll
        for (int t = 0; t < 4; t++) {
            int idx = tid + t * 256;
            int kk = idx >> 6, c = idx & 63;
            Ws[kk][c] = W[(k0 + kk) * 256 + n0 + c];
        }
        __syncthreads();
        #pragma unroll
        for (int kk = 0; kk < 16; kk++) {
            float ra[4], rb[4];
            #pragma unroll
            for (int i = 0; i < 4; i++) ra[i] = As[kk][ty * 4 + i];
            #pragma unroll
            for (int j = 0; j < 4; j++) rb[j] = Ws[kk][tx * 4 + j];
            #pragma unroll
            for (int i = 0; i < 4; i++)
                #pragma unroll
                for (int j = 0; j < 4; j++)
                    acc[i][j] += ra[i] * rb[j];
        }
    }
    #pragma unroll
    for (int i = 0; i < 4; i++) {
        int m = m0 + ty * 4 + i;
        #pragma unroll
        for (int j = 0; j < 4; j++) {
            int n = n0 + tx * 4 + j;
            float v = acc[i][j];
            if (bias) v += bias[n];
            C[m * 256 + n] = v;
        }
    }
}

// ---------------- K1: input projections (Q,K,V and physics a/b) ----------------
__global__ __launch_bounds__(256) void k_proj(
    const float* __restrict__ x,
    const float* __restrict__ Wq, const float* __restrict__ bq,
    const float* __restrict__ Wk, const float* __restrict__ bk,
    const float* __restrict__ Wv, const float* __restrict__ bv,
    const float* __restrict__ Wp1)
{
    __shared__ float As[16][68];
    __shared__ float Ws[16][68];
    int bn = blockIdx.x;        // 0..19
    int bm = blockIdx.y;        // 0..15
    int seg = bn >> 2;
    int n0 = (bn & 3) * 64;

    const float* W; const float* bias; float* C;
    switch (seg) {
        case 0: W = Wq;             bias = bq;      C = g_q; break;
        case 1: W = Wk;             bias = bk;      C = g_k; break;
        case 2: W = Wv;             bias = bv;      C = g_v; break;
        case 3: W = Wp1;            bias = nullptr; C = g_a; break;
        default: W = Wp1 + 256*256; bias = nullptr; C = g_b; break;
    }
    gemm64_body(x, W, bias, C, bm * 64, n0, As, Ws);
}

// ---------------- K2: fused pair scores (qk + gelu-bias MLP + mask) ----------------
#define TBI 8
#define TBJ 8
__global__ __launch_bounds__(256) void k_scores(
    const int* __restrict__ adj,
    const float* __restrict__ bp1,
    const float* __restrict__ Wp2,
    const float* __restrict__ bp2)
{
    // grid: x = j-split (4 x 128 cols), y = i-tile (64), z = b (2)
    int b = blockIdx.z;
    int i0 = blockIdx.y * TBI;
    int j0base = blockIdx.x * 128;
    int tid = threadIdx.x;
    int lane = tid & 31, w = tid >> 5;

    __shared__ float sA[TBI][256];
    __shared__ float sQ[TBI][256];
    __shared__ float sB[TBJ][256];
    __shared__ float sK[TBJ][256];

    // load A,Q rows for this i-tile (contiguous 2048 floats each)
    const float* aptr = g_a + (b * NN + i0) * 256;
    const float* qptr = g_q + (b * NN + i0) * 256;
    #pragma unroll
    for (int t = 0; t < 8; t++) {
        int idx = tid + t * 256;
        ((float*)sA)[idx] = aptr[idx];
        ((float*)sQ)[idx] = qptr[idx];
    }

    // per-lane constants: channel c = lane + 32k
    float bp1r[8];
    float wp2r[8][4];
    #pragma unroll
    for (int k = 0; k < 8; k++) {
        int c = lane + 32 * k;
        bp1r[k] = bp1[c];
        #pragma unroll
        for (int h = 0; h < 4; h++) wp2r[k][h] = Wp2[c * 4 + h];
    }
    float bp2r0 = bp2[0], bp2r1 = bp2[1], bp2r2 = bp2[2], bp2r3 = bp2[3];
    const float scale = 0.125f;   // 64^-0.5
    const float ISQRT2 = 0.70710678118654752f;

    for (int jc = 0; jc < 128; jc += TBJ) {
        int j0 = j0base + jc;
        __syncthreads();
        const float* bptr = g_b + (b * NN + j0) * 256;
        const float* kptr = g_k + (b * NN + j0) * 256;
        #pragma unroll
        for (int t = 0; t < 8; t++) {
            int idx = tid + t * 256;
            ((float*)sB)[idx] = bptr[idx];
            ((float*)sK)[idx] = kptr[idx];
        }
        __syncthreads();

        int j = j0 + w;   // this warp's key index
        // hoist per-lane key-side values
        float bb[8], kv[8];
        #pragma unroll
        for (int k = 0; k < 8; k++) {
            int c = lane + 32 * k;
            bb[k] = sB[w][c] + bp1r[k];
            kv[k] = sK[w][c];
        }

        for (int il = 0; il < TBI; il++) {
            int i = i0 + il;
            int mval = adj[i * NN + j];
            float* outp = &g_attn[((b * NH) * NN + i) * NN + j];
            if (mval == 0) {
                if (lane < 4) outp[lane * NN * NN] = -1e9f;
                continue;
            }
            float aw0 = 0.f, aw1 = 0.f, aw2 = 0.f, aw3 = 0.f;
            float aq0 = 0.f, aq1 = 0.f, aq2 = 0.f, aq3 = 0.f;
            #pragma unroll
            for (int k = 0; k < 8; k++) {
                int c = lane + 32 * k;
                float t = sA[il][c] + bb[k];
                float g = 0.5f * t * (1.0f + erff(t * ISQRT2));
                aw0 += g * wp2r[k][0];
                aw1 += g * wp2r[k][1];
                aw2 += g * wp2r[k][2];
                aw3 += g * wp2r[k][3];
                float qk = sQ[il][c] * kv[k];
                // head = k>>1 (channels [32k,32k+32) lie in head k/2)
                if ((k >> 1) == 0) aq0 += qk;
                else if ((k >> 1) == 1) aq1 += qk;
                else if ((k >> 1) == 2) aq2 += qk;
                else aq3 += qk;
            }
            float s0 = aq0 * scale + aw0 + bp2r0;
            float s1 = aq1 * scale + aw1 + bp2r1;
            float s2 = aq2 * scale + aw2 + bp2r2;
            float s3 = aq3 * scale + aw3 + bp2r3;
            #pragma unroll
            for (int off = 16; off; off >>= 1) {
                s0 += __shfl_xor_sync(0xffffffffu, s0, off);
                s1 += __shfl_xor_sync(0xffffffffu, s1, off);
                s2 += __shfl_xor_sync(0xffffffffu, s2, off);
                s3 += __shfl_xor_sync(0xffffffffu, s3, off);
            }
            if (lane < 4) {
                float sv = (lane == 0) ? s0 : (lane == 1) ? s1 : (lane == 2) ? s2 : s3;
                outp[lane * NN * NN] = sv;
            }
        }
    }
}

// ---------------- K3: softmax over j (warp per row) ----------------
__global__ __launch_bounds__(256) void k_softmax()
{
    int row = blockIdx.x * 8 + (threadIdx.x >> 5);   // B*H*N = 4096 rows
    int lane = threadIdx.x & 31;
    float* p = g_attn + (long)row * NN;

    float4 v[4];
    float mx = -3.4e38f;
    #pragma unroll
    for (int t = 0; t < 4; t++) {
        v[t] = *(const float4*)&p[lane * 4 + t * 128];
        mx = fmaxf(mx, fmaxf(fmaxf(v[t].x, v[t].y), fmaxf(v[t].z, v[t].w)));
    }
    #pragma unroll
    for (int off = 16; off; off >>= 1)
        mx = fmaxf(mx, __shfl_xor_sync(0xffffffffu, mx, off));

    float sum = 0.f;
    #pragma unroll
    for (int t = 0; t < 4; t++) {
        v[t].x = expf(v[t].x - mx);
        v[t].y = expf(v[t].y - mx);
        v[t].z = expf(v[t].z - mx);
        v[t].w = expf(v[t].w - mx);
        sum += v[t].x + v[t].y + v[t].z + v[t].w;
    }
    #pragma unroll
    for (int off = 16; off; off >>= 1)
        sum += __shfl_xor_sync(0xffffffffu, sum, off);
    float inv = 1.0f / sum;
    #pragma unroll
    for (int t = 0; t < 4; t++) {
        v[t].x *= inv; v[t].y *= inv; v[t].z *= inv; v[t].w *= inv;
        *(float4*)&p[lane * 4 + t * 128] = v[t];
    }
}

// ---------------- K4: out = attn @ v  -> ctx[b,i,h*64+d] ----------------
#define TTI 16
__global__ __launch_bounds__(256) void k_av()
{
    int b = blockIdx.z, h = blockIdx.y;
    int i_base = blockIdx.x * TTI;
    int tid = threadIdx.x;

    __shared__ float sP[TTI][512];   // 32 KB
    __shared__ float sV[32][64];     //  8 KB

    const float* attn = g_attn + (((long)(b * NH + h)) * NN + i_base) * NN;
    #pragma unroll
    for (int t = 0; t < 8; t++)
        ((float4*)sP)[tid + t * 256] = ((const float4*)attn)[tid + t * 256];

    int d0 = (tid & 15) * 4;
    int i  = tid >> 4;
    float acc0 = 0.f, acc1 = 0.f, acc2 = 0.f, acc3 = 0.f;

    for (int j0 = 0; j0 < 512; j0 += 32) {
        __syncthreads();
        #pragma unroll
        for (int t = 0; t < 8; t++) {
            int idx = tid + t * 256;
            int r = idx >> 6, c = idx & 63;
            sV[r][c] = g_v[(b * NN + j0 + r) * 256 + h * 64 + c];
        }
        __syncthreads();
        #pragma unroll 8
        for (int j = 0; j < 32; j++) {
            float pv = sP[i][j0 + j];
            float4 vv = *(const float4*)&sV[j][d0];
            acc0 += pv * vv.x;
            acc1 += pv * vv.y;
            acc2 += pv * vv.z;
            acc3 += pv * vv.w;
        }
    }
    float4 r4 = make_float4(acc0, acc1, acc2, acc3);
    *(float4*)&g_ctx[(b * NN + i_base + i) * 256 + h * 64 + d0] = r4;
}

// ---------------- K5: final projection ----------------
__global__ __launch_bounds__(256) void k_out(
    const float* __restrict__ Wo, const float* __restrict__ bo,
    float* __restrict__ out)
{
    __shared__ float As[16][68];
    __shared__ float Ws[16][68];
    gemm64_body(g_ctx, Wo, bo, out, blockIdx.y * 64, blockIdx.x * 64, As, Ws);
}

// ---------------- launch ----------------
extern "C" void kernel_launch(void* const* d_in, const int* in_sizes, int n_in,
                              void* d_out, int out_size)
{
    const float* x   = (const float*)d_in[0];
    const int*   adj = (const int*)  d_in[1];
    const float* Wq  = (const float*)d_in[2];
    const float* bq  = (const float*)d_in[3];
    const float* Wk  = (const float*)d_in[4];
    const float* bk  = (const float*)d_in[5];
    const float* Wv  = (const float*)d_in[6];
    const float* bv  = (const float*)d_in[7];
    const float* Wo  = (const float*)d_in[8];
    const float* bo  = (const float*)d_in[9];
    const float* Wp1 = (const float*)d_in[10];
    const float* bp1 = (const float*)d_in[11];
    const float* Wp2 = (const float*)d_in[12];
    const float* bp2 = (const float*)d_in[13];
    float* out = (float*)d_out;

    dim3 g1(20, 16);
    k_proj<<<g1, 256>>>(x, Wq, bq, Wk, bk, Wv, bv, Wp1);

    dim3 g2(4, 64, 2);
    k_scores<<<g2, 256>>>(adj, bp1, Wp2, bp2);

    k_softmax<<<512, 256>>>();

    dim3 g4(32, 4, 2);
    k_av<<<g4, 256>>>();

    dim3 g5(4, 16);
    k_out<<<g5, 256>>>(Wo, bo, out);
}